// round 12
// baseline (speedup 1.0000x reference)
#include <cuda_runtime.h>
#include <cstdint>
#include <cstddef>

// Problem constants
#define NB   8
#define CB   128
#define NC   1024          // NB*CB
#define HH   160
#define WW   160
#define NA   180
#define NR   180
#define AR   (NA*NR)       // 32400
#define PIX  (HH*WW)       // 25600
#define WR   16            // staged rho-window rows (16x8 tile span <= 15)
#define PH   3             // angles per staging phase
#define NPHASE (NA/PH)     // 60
#define TPB  256
#define BUFB (PH*WR*512)   // 24576 B per buffer

// Scratch in __device__ globals (no allocation allowed)
__device__ float         g_T[(size_t)AR * NC];       // transposed: T[a][r][nc]
__device__ unsigned char g_idx[(size_t)NA * PIX];    // r index table [a][y][x]
__device__ double        g_tab[2 * NA];              // cos/irho, sin/irho

// ---- sorted 4x4-block walk orders (px = x + 4y), one per tan-theta class ----
// boundaries: tan = 1/3, 1/2, 2/3, 1, 3/2, 2, 3 (mirrored for theta > 90)
#define ORD_Q0 0,4,8,12,1,5,9,13,2,6,10,14,3,7,11,15
#define ORD_Q1 0,4,8,1,12,5,9,2,13,6,10,3,14,7,11,15
#define ORD_Q2 0,4,1,8,5,12,2,9,6,13,3,10,7,14,11,15
#define ORD_Q3 0,4,1,8,5,2,12,9,6,3,13,10,7,14,11,15
#define ORD_Q4 0,1,4,2,5,8,3,6,9,12,7,10,13,11,14,15
#define ORD_Q5 0,1,4,2,5,3,8,6,9,7,12,10,13,11,14,15
#define ORD_Q6 0,1,2,4,3,5,6,8,7,9,10,12,11,13,14,15
#define ORD_Q7 0,1,2,3,4,5,6,7,8,9,10,11,12,13,14,15

#define PK(A,B,C,D,E,F,G,H,I,J,K,L,M,N,O,P) \
  ( (unsigned long long)(A)        | ((unsigned long long)(B)<<4)  | \
    ((unsigned long long)(C)<<8)   | ((unsigned long long)(D)<<12) | \
    ((unsigned long long)(E)<<16)  | ((unsigned long long)(F)<<20) | \
    ((unsigned long long)(G)<<24)  | ((unsigned long long)(H)<<28) | \
    ((unsigned long long)(I)<<32)  | ((unsigned long long)(J)<<36) | \
    ((unsigned long long)(K)<<40)  | ((unsigned long long)(L)<<44) | \
    ((unsigned long long)(M)<<48)  | ((unsigned long long)(N)<<52) | \
    ((unsigned long long)(O)<<56)  | ((unsigned long long)(P)<<60) )
#define PKX(...) PK(__VA_ARGS__)

__device__ const unsigned long long c_ord64[8] = {
    PKX(ORD_Q0), PKX(ORD_Q1), PKX(ORD_Q2), PKX(ORD_Q3),
    PKX(ORD_Q4), PKX(ORD_Q5), PKX(ORD_Q6), PKX(ORD_Q7)
};

// ---------------------------------------------------------------------------
// Kernel 0: trig table (fp64, once)
// ---------------------------------------------------------------------------
__global__ void tab_kernel()
{
    int a = threadIdx.x;
    if (a < NA) {
        const double PI = 3.14159265358979323846;
        double th = (double)a * (PI / 180.0);
        double irho = 227.0 / 180.0;   // (int(sqrt(160^2+160^2))+1)/180
        g_tab[a]      = cos(th) / irho;
        g_tab[NA + a] = sin(th) / irho;
    }
}

// ---------------------------------------------------------------------------
// Kernel 1: rho-index table (fp64 FMA-class ops only; matches numpy exactly)
// ---------------------------------------------------------------------------
__global__ void build_idx_kernel()
{
    const int a = blockIdx.y;
    double tc = g_tab[a], ts = g_tab[NA + a];
    int p = blockIdx.x * 256 + threadIdx.x;
    int y = p / WW, x = p - y * WW;
    double v = __dadd_rn(__dmul_rn((double)(x - 80), tc),
                         __dmul_rn((double)(y - 80), ts));
    int r = (int)rint(v) + 90;
    r = min(NR - 1, max(0, r));
    g_idx[(size_t)a * PIX + p] = (unsigned char)r;
}

// ---------------------------------------------------------------------------
// Kernel 2: transpose In[NC][AR] -> T[AR][NC]
// ---------------------------------------------------------------------------
__global__ void transpose_kernel(const float* __restrict__ in)
{
    __shared__ float tile[32][33];
    int ar0 = blockIdx.x * 32;
    int nc0 = blockIdx.y * 32;
    int tx = threadIdx.x;
    int ty = threadIdx.y;
    #pragma unroll
    for (int i = ty; i < 32; i += 8) {
        int ar = ar0 + tx;
        if (ar < AR) tile[i][tx] = in[(size_t)(nc0 + i) * AR + ar];
    }
    __syncthreads();
    #pragma unroll
    for (int i = ty; i < 32; i += 8) {
        int ar = ar0 + i;
        if (ar < AR) g_T[(size_t)ar * NC + nc0 + tx] = tile[tx][i];
    }
}

// ---------------------------------------------------------------------------
// Kernel 3: main inverse-Hough.
//   CTA = 16x8 pixel tile x 128 ch, 256 thr = 8 warps, 3 CTAs/SM.
//   Warp = one 4x4 pixel block; lane = 4 consecutive channels.
//   Sorted 16-px walk per tan-theta class (boundaries snapped to 3-angle
//   phases; 2-bit signed deltas absorb boundary mis-sorts) -> ~4 value
//   loads per 16 px per angle: wavefronts/px cut 1.5 -> 1.0 vs 4x2.
//   Double-buffered cp.async staging (WR=16 rows x 3 angles), R9-style.
// ---------------------------------------------------------------------------
__device__ __forceinline__ void cp16(unsigned smem_addr, const void* gptr)
{
    asm volatile("cp.async.cg.shared.global [%0], [%1], 16;\n"
                 :: "r"(smem_addr), "l"(gptr));
}

__global__ void __launch_bounds__(TPB, 3) iht_main_kernel(float* __restrict__ out)
{
    __shared__ __align__(16) char sbuf[2][BUFB];     // 49152 B
    __shared__ uint2 sw2[8 * NA];                    // 11520 B
    __shared__ unsigned char sbase[192];

    const int tid = threadIdx.x;
    const int x0 = blockIdx.x * 16;
    const int y0 = blockIdx.y * 8;
    const int cz0 = blockIdx.z * 128;
    const int lane = tid & 31;
    const int w = tid >> 5;                          // warp = 4x4 block id

    // ---- per-angle window base (min over tile corners; affine => corners) ----
    if (tid < NA) {
        const unsigned char* s = g_idx + (size_t)tid * PIX + y0 * WW + x0;
        int m = min(min((int)s[0], (int)s[15]),
                    min((int)s[7 * WW], (int)s[7 * WW + 15]));
        sbase[tid] = (unsigned char)min(m, NR - WR);
    }
    __syncthreads();

    // ---- staging (R9-style fixed span, double buffer) ----
    auto stage = [&](int f) {
        int a0 = f * PH;
        unsigned sd = (unsigned)__cvta_generic_to_shared(sbuf[f & 1]);
        #pragma unroll
        for (int it = 0; it < 6; it++) {
            int e = tid + it * TPB;                  // 1536 slots of 16B
            int s   = e >> 9;
            int rem = e & 511;
            int row = rem >> 5;
            int c   = rem & 31;
            int a = a0 + s;
            int r = (int)sbase[a] + row;
            cp16(sd + (e << 4),
                 g_T + ((size_t)a * NR + r) * NC + cz0 + c * 4);
        }
        asm volatile("cp.async.commit_group;\n" ::: "memory");
    };

    stage(0);

    // ---- build walk records: rel0(5b) + 15 x 2b signed deltas ----
    for (int i = tid; i < 8 * NA; i += TPB) {
        int blk = i & 7, a = i >> 3;
        int cls = a < 18 ? 0 : a < 27 ? 1 : a < 33 ? 2 : a < 45 ? 3
                : a < 57 ? 4 : a < 63 ? 5 : a < 72 ? 6 : a < 90 ? 7
                : a < 108 ? 8 : a < 117 ? 9 : a < 123 ? 10 : a < 135 ? 11
                : a < 147 ? 12 : a < 153 ? 13 : a < 162 ? 14 : 15;
        int mir = cls >= 8;
        unsigned long long ord = c_ord64[mir ? (15 - cls) : cls];
        const unsigned char* s = g_idx + (size_t)a * PIX
                                 + (y0 + 4 * (blk >> 2)) * WW + x0 + 4 * (blk & 3);
        unsigned t0 = *(const unsigned*)s;
        unsigned t1 = *(const unsigned*)(s + WW);
        unsigned t2 = *(const unsigned*)(s + 2 * WW);
        unsigned t3 = *(const unsigned*)(s + 3 * WW);
        unsigned wv0 = 0, wv1 = 0;
        int prev = 0;
        #pragma unroll
        for (int k = 0; k < 16; k++) {
            int p = (int)((ord >> (4 * k)) & 15ull);
            if (mir) p = (3 - (p & 3)) | (p & 12);
            unsigned rowv = (p < 4) ? t0 : (p < 8) ? t1 : (p < 12) ? t2 : t3;
            int cur = (int)((rowv >> (8 * (p & 3))) & 255u);
            if (k == 0) {
                wv0 = (unsigned)(cur - (int)sbase[a]);       // rel0, 5 bits
            } else {
                int d = (cur - prev) & 3;                    // signed 2-bit
                if (k <= 13) wv0 |= (unsigned)d << (5 + 2 * (k - 1));
                else         wv1 |= (unsigned)d << (2 * (k - 14));
            }
            prev = cur;
        }
        sw2[blk * NA + a] = make_uint2(wv0, wv1);
    }
    __syncthreads();

    // ---- accumulators: 16 px x 4 ch = 32 u64 (px = x + 4y) ----
    unsigned long long acc[32];
    #pragma unroll
    for (int i = 0; i < 32; i++) acc[i] = 0ull;

#define STEP0(PX)                                                             \
    asm volatile("{\n\t"                                                      \
        ".reg .u32 rr;\n\t"                                                   \
        "bfe.u32 rr, %5, 0, 5;\n\t"                                           \
        "mad.lo.u32 %4, rr, 512, %6;\n\t"                                     \
        "ld.shared.v2.u64 {%2, %3}, [%4];\n\t"                                \
        "add.rn.f32x2 %0, %0, %2;\n\t"                                        \
        "add.rn.f32x2 %1, %1, %3;\n\t"                                        \
        "}"                                                                   \
        : "+l"(acc[2*(PX)]), "+l"(acc[2*(PX)+1]),                             \
          "+l"(v0), "+l"(v1), "=r"(ad)                                        \
        : "r"(wv0), "r"(sA))

#define STEPW(PX, WREG, OFF)                                                  \
    asm volatile("{\n\t"                                                      \
        ".reg .pred p;\n\t .reg .s32 d;\n\t"                                  \
        "bfe.s32 d, %5, %6, 2;\n\t"                                           \
        "setp.ne.s32 p, d, 0;\n\t"                                            \
        "mad.lo.s32 %4, d, 512, %4;\n\t"                                      \
        "@p ld.shared.v2.u64 {%2, %3}, [%4];\n\t"                             \
        "add.rn.f32x2 %0, %0, %2;\n\t"                                        \
        "add.rn.f32x2 %1, %1, %3;\n\t"                                        \
        "}"                                                                   \
        : "+l"(acc[2*(PX)]), "+l"(acc[2*(PX)+1]),                             \
          "+l"(v0), "+l"(v1), "+r"(ad)                                        \
        : "r"(WREG), "n"(OFF))

#define DOSEG(F0, F1, P0,P1,P2,P3,P4,P5,P6,P7,P8,P9,P10,P11,P12,P13,P14,P15)  \
    for (int f = (F0); f < (F1); f++) {                                       \
        asm volatile("cp.async.wait_group 0;\n" ::: "memory");                \
        __syncthreads();                                                      \
        if (f + 1 < NPHASE) stage(f + 1);                                     \
        unsigned bufa = bufa0 + (unsigned)((f & 1) * BUFB);                   \
        _Pragma("unroll")                                                     \
        for (int s2 = 0; s2 < PH; s2++) {                                     \
            uint2 wvp = sw2[swb + f * PH + s2];                               \
            unsigned wv0 = wvp.x, wv1 = wvp.y;                                \
            unsigned sA = bufa + (unsigned)(s2 * (WR * 512));                 \
            unsigned long long v0 = 0, v1 = 0;                                \
            unsigned ad;                                                      \
            STEP0(P0);                                                        \
            STEPW(P1,  wv0,  5); STEPW(P2,  wv0,  7); STEPW(P3,  wv0,  9);    \
            STEPW(P4,  wv0, 11); STEPW(P5,  wv0, 13); STEPW(P6,  wv0, 15);    \
            STEPW(P7,  wv0, 17); STEPW(P8,  wv0, 19); STEPW(P9,  wv0, 21);    \
            STEPW(P10, wv0, 23); STEPW(P11, wv0, 25); STEPW(P12, wv0, 27);    \
            STEPW(P13, wv0, 29); STEPW(P14, wv1,  0); STEPW(P15, wv1,  2);    \
        }                                                                     \
    }

#define MM(P) ((3 - ((P) & 3)) | ((P) & 12))
#define DOSEGM(F0, F1, P0,P1,P2,P3,P4,P5,P6,P7,P8,P9,P10,P11,P12,P13,P14,P15) \
    DOSEG(F0, F1, MM(P0),MM(P1),MM(P2),MM(P3),MM(P4),MM(P5),MM(P6),MM(P7),    \
          MM(P8),MM(P9),MM(P10),MM(P11),MM(P12),MM(P13),MM(P14),MM(P15))
#define DOSEGX(F0, F1, ...)  DOSEG(F0, F1, __VA_ARGS__)
#define DOSEGMX(F0, F1, ...) DOSEGM(F0, F1, __VA_ARGS__)

    const unsigned swb = w * NA;
    unsigned bufa0 = (unsigned)__cvta_generic_to_shared(sbuf[0]) + (lane << 4);

    DOSEGX (  0,  6, ORD_Q0);
    DOSEGX (  6,  9, ORD_Q1);
    DOSEGX (  9, 11, ORD_Q2);
    DOSEGX ( 11, 15, ORD_Q3);
    DOSEGX ( 15, 19, ORD_Q4);
    DOSEGX ( 19, 21, ORD_Q5);
    DOSEGX ( 21, 24, ORD_Q6);
    DOSEGX ( 24, 30, ORD_Q7);
    DOSEGMX( 30, 36, ORD_Q7);
    DOSEGMX( 36, 39, ORD_Q6);
    DOSEGMX( 39, 41, ORD_Q5);
    DOSEGMX( 41, 45, ORD_Q4);
    DOSEGMX( 45, 49, ORD_Q3);
    DOSEGMX( 49, 51, ORD_Q2);
    DOSEGMX( 51, 54, ORD_Q1);
    DOSEGMX( 54, 60, ORD_Q0);
#undef DOSEGX
#undef DOSEGMX
#undef DOSEGM
#undef DOSEG
#undef STEPW
#undef STEP0

    // ---- epilogue: per ch, per row: float4 over the 4-wide block ----
    const int gx = x0 + 4 * (w & 3);
    const int gy = y0 + 4 * (w >> 2);
    const int c0 = cz0 + lane * 4;
    #pragma unroll
    for (int y = 0; y < 4; y++) {
        #pragma unroll
        for (int cc = 0; cc < 4; cc++) {
            int half = cc & 1, sel = cc >> 1;
            float4 o;
            unsigned long long s0 = acc[(0 + 4*y)*2 + sel];
            unsigned long long s1 = acc[(1 + 4*y)*2 + sel];
            unsigned long long s2 = acc[(2 + 4*y)*2 + sel];
            unsigned long long s3 = acc[(3 + 4*y)*2 + sel];
            o.x = __uint_as_float(half ? (unsigned)(s0 >> 32) : (unsigned)s0);
            o.y = __uint_as_float(half ? (unsigned)(s1 >> 32) : (unsigned)s1);
            o.z = __uint_as_float(half ? (unsigned)(s2 >> 32) : (unsigned)s2);
            o.w = __uint_as_float(half ? (unsigned)(s3 >> 32) : (unsigned)s3);
            *(float4*)(out + (size_t)(c0 + cc) * PIX + (gy + y) * WW + gx) = o;
        }
    }
}

// ---------------------------------------------------------------------------
extern "C" void kernel_launch(void* const* d_in, const int* in_sizes, int n_in,
                              void* d_out, int out_size)
{
    const float* hough = (const float*)d_in[0];
    float* out = (float*)d_out;

    tab_kernel<<<1, 256>>>();
    build_idx_kernel<<<dim3(PIX / 256, NA), 256>>>();
    transpose_kernel<<<dim3((AR + 31) / 32, NC / 32), dim3(32, 8)>>>(hough);
    iht_main_kernel<<<dim3(10, 20, 8), TPB>>>(out);
}